// round 7
// baseline (speedup 1.0000x reference)
#include <cuda_runtime.h>
#include <cuda_bf16.h>
#include <cstdint>

// ---------------------------------------------------------------------------
// MoE (top-2 of 8 experts), SwiGLU MLP, fp32 in/out, TF32 tensor-core compute.
//   T=2048 tokens, H=2048 hidden, I=1408 inter, E=8, K=2.
// Pipeline:
//   route_kernel   : per-expert contiguous slot lists + M-tile map
//   round_x_kernel : g_xr = tf32_round(hidden_states)      (read 22x by gemm1)
//   gemm1_kernel   : act[slot, I] = silu(X@Wg) * (X@Wu)    (gathered, fused)
//                    -> stored PRE-ROUNDED to tf32          (read 32x by gemm2)
//   gemm2_kernel   : out[tok, H] += w_slot * (act @ Wd)    (atomic scatter)
// Convert-once discipline: multiply-reused operands rounded to tf32 once at
// their producer -> A-paths are plain copies -> moved onto cp.async (LDGSTS).
// ---------------------------------------------------------------------------

#define T_TOK   2048
#define HID     2048
#define INTER   1408
#define NEXP    8
#define TOPK    2
#define NSLOT   (T_TOK * TOPK)   // 4096

#define BM      128
#define BN      64
#define BK      16
#define NTHREADS 256
#define MAXTILES 40              // sum ceil(cnt_e/128) <= 4096/128 + 8 = 40
#define AST     20               // padded A smem stride (row = 80 B = 5x16 -> cp.async-aligned)
#define BST     72               // padded B smem stride (stride % 32 == 8 -> conflict-free)
#define ABUFB   (BM * AST * 4)   // bytes per A buffer (10240)

// ------------------------- device scratch (no allocs) ----------------------
__device__ int   g_cnt[NEXP];
__device__ int   g_off[NEXP];
__device__ int   g_ntiles;
__device__ int   g_tile_e[MAXTILES];
__device__ int   g_tile_m0[MAXTILES];
__device__ int   g_tok[NSLOT];
__device__ float g_w[NSLOT];
__device__ float g_xr [(size_t)T_TOK * HID];     // 16 MB tf32-rounded X
__device__ float g_act[(size_t)NSLOT * INTER];   // ~23 MB SwiGLU acts (tf32-rounded)

// ------------------------- helpers -----------------------------------------
__device__ __forceinline__ float to_tf32(float x) {
    // Round-to-nearest fp32->tf32. Mandatory: raw-bit truncation in the MMA
    // introduces a correlated magnitude bias (~-5e-4 per GEMM) that would
    // push the chained two-GEMM error toward the 1e-3 threshold.
    uint32_t u;
    asm("cvt.rna.tf32.f32 %0, %1;" : "=r"(u) : "f"(x));
    return __uint_as_float(u);
}

__device__ __forceinline__ void cp_async16(uint32_t saddr, const void* gptr) {
    asm volatile("cp.async.ca.shared.global [%0], [%1], 16;"
                 :: "r"(saddr), "l"(gptr) : "memory");
}
__device__ __forceinline__ void cp_async_commit() {
    asm volatile("cp.async.commit_group;" ::: "memory");
}
__device__ __forceinline__ void cp_async_wait_all() {
    asm volatile("cp.async.wait_group 0;" ::: "memory");
}

#define MMA_TF32(c, a, b0, b1)                                             \
    asm volatile(                                                          \
        "mma.sync.aligned.m16n8k8.row.col.f32.tf32.tf32.f32 "              \
        "{%0,%1,%2,%3}, {%4,%5,%6,%7}, {%8,%9}, {%0,%1,%2,%3};"            \
        : "+f"((c)[0]), "+f"((c)[1]), "+f"((c)[2]), "+f"((c)[3])           \
        : "r"((a)[0]), "r"((a)[1]), "r"((a)[2]), "r"((a)[3]),              \
          "r"(b0), "r"(b1))

// ------------------------- X pre-rounding -----------------------------------
__global__ void round_x_kernel(const float* __restrict__ X) {
    size_t i = ((size_t)blockIdx.x * blockDim.x + threadIdx.x) * 4;
    const size_t n = (size_t)T_TOK * HID;
    if (i < n) {
        float4 v = *(const float4*)(X + i);
        v.x = to_tf32(v.x); v.y = to_tf32(v.y);
        v.z = to_tf32(v.z); v.w = to_tf32(v.w);
        *(float4*)(g_xr + i) = v;
    }
}

// ------------------------- routing ------------------------------------------
__global__ void route_kernel(const int* __restrict__ topk_idx,
                             const float* __restrict__ topk_w) {
    __shared__ int s_cnt[NEXP];
    __shared__ int s_off[NEXP];
    __shared__ int s_fill[NEXP];
    int tid = threadIdx.x;

    if (tid < NEXP) { s_cnt[tid] = 0; s_fill[tid] = 0; }
    __syncthreads();

    for (int s = tid; s < NSLOT; s += blockDim.x)
        atomicAdd(&s_cnt[topk_idx[s]], 1);
    __syncthreads();

    if (tid == 0) {
        int acc = 0, nt = 0;
        for (int e = 0; e < NEXP; e++) {
            s_off[e] = acc;
            g_off[e] = acc;
            g_cnt[e] = s_cnt[e];
            for (int m0 = 0; m0 < s_cnt[e]; m0 += BM) {
                g_tile_e[nt] = e;
                g_tile_m0[nt] = m0;
                nt++;
            }
            acc += s_cnt[e];
        }
        g_ntiles = nt;
        for (int t = nt; t < MAXTILES; t++) { g_tile_e[t] = 0; g_tile_m0[t] = 0; }
    }
    __syncthreads();

    for (int s = tid; s < NSLOT; s += blockDim.x) {
        int e = topk_idx[s];
        int p = atomicAdd(&s_fill[e], 1);
        int slot = s_off[e] + p;
        g_tok[slot] = s >> 1;          // token id (TOPK = 2)
        g_w[slot]   = topk_w[s];
    }
}

// ------------------------- GEMM1: fused gate+up + SwiGLU --------------------
// act[seg+m, i] = silu(sum_h X[tok,h]*Wg[e,h,i]) * (sum_h X[tok,h]*Wu[e,h,i])
__global__ __launch_bounds__(NTHREADS, 2) void gemm1_kernel(
    const float* __restrict__ Wg_all,
    const float* __restrict__ Wu_all) {
    int tile = blockIdx.x;
    if (tile >= g_ntiles) return;
    int e   = g_tile_e[tile];
    int m0  = g_tile_m0[tile];
    int seg = g_off[e];
    int cnt = g_cnt[e];
    int n0  = blockIdx.y * BN;

    __shared__ float As [2][BM][AST];
    __shared__ float Bgs[2][BK][BST];
    __shared__ float Bus[2][BK][BST];
    __shared__ int   s_tok[BM];

    int tid = threadIdx.x;
    if (tid < BM) {
        int ml = m0 + tid;
        s_tok[tid] = g_tok[seg + (ml < cnt ? ml : 0)];
    }
    __syncthreads();

    const int arow = tid >> 2, acol = (tid & 3) << 2;   // A: 128x16, 2 x 16B/thread
    const int brow = tid >> 4, bcol = (tid & 15) << 2;  // B: 16x64,  1 float4/thread
    const int arow2 = arow + 64;

    // hoisted pointers; A from pre-rounded X via cp.async
    const float* aptr0 = g_xr + (size_t)s_tok[arow]  * HID + acol;
    const float* aptr1 = g_xr + (size_t)s_tok[arow2] * HID + acol;
    const float* bgptr = Wg_all + (size_t)e * HID * INTER + (size_t)brow * INTER + n0 + bcol;
    const float* buptr = Wu_all + (size_t)e * HID * INTER + (size_t)brow * INTER + n0 + bcol;

    const uint32_t sa0 = (uint32_t)__cvta_generic_to_shared(&As[0][arow ][acol]);
    const uint32_t sa1 = (uint32_t)__cvta_generic_to_shared(&As[0][arow2][acol]);

    float4 rg, ru;

    auto cpA = [&](int b, int kt) {
        size_t k0 = (size_t)kt * BK;
        cp_async16(sa0 + b * ABUFB, aptr0 + k0);
        cp_async16(sa1 + b * ABUFB, aptr1 + k0);
    };
    auto gloadB = [&](int kt) {
        size_t k0 = (size_t)kt * BK;
        rg = *(const float4*)(bgptr + k0 * INTER);
        ru = *(const float4*)(buptr + k0 * INTER);
    };
    auto sstoreB = [&](int b) {
        Bgs[b][brow][bcol+0] = to_tf32(rg.x);  Bgs[b][brow][bcol+1] = to_tf32(rg.y);
        Bgs[b][brow][bcol+2] = to_tf32(rg.z);  Bgs[b][brow][bcol+3] = to_tf32(rg.w);
        Bus[b][brow][bcol+0] = to_tf32(ru.x);  Bus[b][brow][bcol+1] = to_tf32(ru.y);
        Bus[b][brow][bcol+2] = to_tf32(ru.z);  Bus[b][brow][bcol+3] = to_tf32(ru.w);
    };

    const int lane = tid & 31, wid = tid >> 5;
    const int wm = (wid & 3) << 5;   // warp M offset: 0/32/64/96
    const int wn = (wid >> 2) << 5;  // warp N offset: 0/32
    const int qr = lane >> 2, qc = lane & 3;

    float cg[2][4][4], cu[2][4][4];
#pragma unroll
    for (int i = 0; i < 2; i++)
#pragma unroll
        for (int j = 0; j < 4; j++)
#pragma unroll
            for (int v = 0; v < 4; v++) { cg[i][j][v] = 0.f; cu[i][j][v] = 0.f; }

    auto compute = [&](int b) {
#pragma unroll
        for (int kk = 0; kk < BK; kk += 8) {
            uint32_t a[2][4];
#pragma unroll
            for (int im = 0; im < 2; im++) {
                int r = wm + im * 16 + qr;
                a[im][0] = __float_as_uint(As[b][r    ][kk + qc    ]);
                a[im][1] = __float_as_uint(As[b][r + 8][kk + qc    ]);
                a[im][2] = __float_as_uint(As[b][r    ][kk + qc + 4]);
                a[im][3] = __float_as_uint(As[b][r + 8][kk + qc + 4]);
            }
#pragma unroll
            for (int jn = 0; jn < 4; jn++) {
                int c = wn + jn * 8 + qr;
                uint32_t bg0 = __float_as_uint(Bgs[b][kk + qc    ][c]);
                uint32_t bg1 = __float_as_uint(Bgs[b][kk + qc + 4][c]);
                uint32_t bu0 = __float_as_uint(Bus[b][kk + qc    ][c]);
                uint32_t bu1 = __float_as_uint(Bus[b][kk + qc + 4][c]);
#pragma unroll
                for (int im = 0; im < 2; im++) {
                    MMA_TF32(cg[im][jn], a[im], bg0, bg1);
                    MMA_TF32(cu[im][jn], a[im], bu0, bu1);
                }
            }
        }
    };

    // Pipelined mainloop, one barrier per iter. A arrives via cp.async into
    // buf^1 (WAR on buf^1 fenced by the previous barrier); wait_group 0 +
    // barrier orders it before the next compute. B converts through regs.
    const int NK = HID / BK;   // 128
    cpA(0, 0);
    gloadB(0);
    sstoreB(0);
    cp_async_commit();
    cp_async_wait_all();
    __syncthreads();
    int buf = 0;
#pragma unroll 1
    for (int kt = 0; kt < NK - 1; kt++) {
        cpA(buf ^ 1, kt + 1);
        cp_async_commit();
        gloadB(kt + 1);
        compute(buf);
        sstoreB(buf ^ 1);
        cp_async_wait_all();
        __syncthreads();
        buf ^= 1;
    }
    compute(buf);

    // epilogue: SwiGLU, store PRE-ROUNDED tf32 to g_act (read 32x by gemm2).
#pragma unroll
    for (int im = 0; im < 2; im++) {
#pragma unroll
        for (int v2 = 0; v2 < 2; v2++) {
            int r  = wm + im * 16 + qr + v2 * 8;
            int ml = m0 + r;
            if (ml < cnt) {
                float* dst = g_act + (size_t)(seg + ml) * INTER + n0;
#pragma unroll
                for (int jn = 0; jn < 4; jn++) {
                    int c = wn + jn * 8 + qc * 2;
                    float g0 = cg[im][jn][v2 * 2], g1 = cg[im][jn][v2 * 2 + 1];
                    float u0 = cu[im][jn][v2 * 2], u1 = cu[im][jn][v2 * 2 + 1];
                    dst[c    ] = to_tf32(u0 * __fdividef(g0, 1.f + __expf(-g0)));
                    dst[c + 1] = to_tf32(u1 * __fdividef(g1, 1.f + __expf(-g1)));
                }
            }
        }
    }
}

// ------------------------- GEMM2: down proj + weighted scatter --------------
__global__ __launch_bounds__(NTHREADS, 2) void gemm2_kernel(
    const float* __restrict__ Wd_all,
    float* __restrict__ out) {
    int tile = blockIdx.x;
    if (tile >= g_ntiles) return;
    int e   = g_tile_e[tile];
    int m0  = g_tile_m0[tile];
    int seg = g_off[e];
    int cnt = g_cnt[e];
    int n0  = blockIdx.y * BN;

    __shared__ float As[2][BM][AST];
    __shared__ float Bs[2][BK][BST];
    __shared__ int   s_tok[BM];
    __shared__ float s_w[BM];

    int tid = threadIdx.x;
    if (tid < BM) {
        int ml = m0 + tid;
        int sl = seg + (ml < cnt ? ml : 0);
        s_tok[tid] = g_tok[sl];
        s_w[tid]   = g_w[sl];
    }

    const int arow = tid >> 2, acol = (tid & 3) << 2;
    const int brow = tid >> 4, bcol = (tid & 15) << 2;
    // clamp rows beyond segment to a valid act row (results masked in epilogue)
    const int ar0 = seg + (m0 + arow      < cnt ? m0 + arow      : cnt - 1);
    const int ar1 = seg + (m0 + arow + 64 < cnt ? m0 + arow + 64 : cnt - 1);

    const float* aptr0 = g_act + (size_t)ar0 * INTER + acol;
    const float* aptr1 = g_act + (size_t)ar1 * INTER + acol;
    const float* bptr  = Wd_all + (size_t)e * INTER * HID + (size_t)brow * HID + n0 + bcol;

    const uint32_t sa0 = (uint32_t)__cvta_generic_to_shared(&As[0][arow     ][acol]);
    const uint32_t sa1 = (uint32_t)__cvta_generic_to_shared(&As[0][arow + 64][acol]);

    float4 rb;

    auto cpA = [&](int b, int kt) {
        size_t k0 = (size_t)kt * BK;
        cp_async16(sa0 + b * ABUFB, aptr0 + k0);
        cp_async16(sa1 + b * ABUFB, aptr1 + k0);
    };
    auto gloadB = [&](int kt) {
        size_t k0 = (size_t)kt * BK;
        rb = *(const float4*)(bptr + k0 * HID);
    };
    auto sstoreB = [&](int b) {
        Bs[b][brow][bcol+0] = to_tf32(rb.x); Bs[b][brow][bcol+1] = to_tf32(rb.y);
        Bs[b][brow][bcol+2] = to_tf32(rb.z); Bs[b][brow][bcol+3] = to_tf32(rb.w);
    };

    const int lane = tid & 31, wid = tid >> 5;
    const int wm = (wid & 3) << 5;
    const int wn = (wid >> 2) << 5;
    const int qr = lane >> 2, qc = lane & 3;

    float cd[2][4][4];
#pragma unroll
    for (int i = 0; i < 2; i++)
#pragma unroll
        for (int j = 0; j < 4; j++)
#pragma unroll
            for (int v = 0; v < 4; v++) cd[i][j][v] = 0.f;

    auto compute = [&](int b) {
#pragma unroll
        for (int kk = 0; kk < BK; kk += 8) {
            uint32_t a[2][4];
#pragma unroll
            for (int im = 0; im < 2; im++) {
                int r = wm + im * 16 + qr;
                a[im][0] = __float_as_uint(As[b][r    ][kk + qc    ]);
                a[im][1] = __float_as_uint(As[b][r + 8][kk + qc    ]);
                a[im][2] = __float_as_uint(As[b][r    ][kk + qc + 4]);
                a[im][3] = __float_as_uint(As[b][r + 8][kk + qc + 4]);
            }
#pragma unroll
            for (int jn = 0; jn < 4; jn++) {
                int c = wn + jn * 8 + qr;
                uint32_t b0 = __float_as_uint(Bs[b][kk + qc    ][c]);
                uint32_t b1 = __float_as_uint(Bs[b][kk + qc + 4][c]);
#pragma unroll
                for (int im = 0; im < 2; im++) {
                    MMA_TF32(cd[im][jn], a[im], b0, b1);
                }
            }
        }
    };

    __syncthreads();   // s_tok/s_w + clamped pointers valid before first cpA
    const int NK = INTER / BK;   // 88
    cpA(0, 0);
    gloadB(0);
    sstoreB(0);
    cp_async_commit();
    cp_async_wait_all();
    __syncthreads();
    int buf = 0;
#pragma unroll 1
    for (int kt = 0; kt < NK - 1; kt++) {
        cpA(buf ^ 1, kt + 1);
        cp_async_commit();
        gloadB(kt + 1);
        compute(buf);
        sstoreB(buf ^ 1);
        cp_async_wait_all();
        __syncthreads();
        buf ^= 1;
    }
    compute(buf);

    // epilogue: weighted atomic scatter into out
#pragma unroll
    for (int im = 0; im < 2; im++) {
#pragma unroll
        for (int v2 = 0; v2 < 2; v2++) {
            int r  = wm + im * 16 + qr + v2 * 8;
            int ml = m0 + r;
            if (ml < cnt) {
                float wgt = s_w[r];
                float* dst = out + (size_t)s_tok[r] * HID + n0;
#pragma unroll
                for (int jn = 0; jn < 4; jn++) {
                    int c = wn + jn * 8 + qc * 2;
                    atomicAdd(&dst[c    ], wgt * cd[im][jn][v2 * 2]);
                    atomicAdd(&dst[c + 1], wgt * cd[im][jn][v2 * 2 + 1]);
                }
            }
        }
    }
}

// ------------------------- launch -------------------------------------------
extern "C" void kernel_launch(void* const* d_in, const int* in_sizes, int n_in,
                              void* d_out, int out_size) {
    const float* X   = (const float*)d_in[0];   // hidden_states [T, H]
    const int*   idx = (const int*)  d_in[1];   // top_k_index   [T, 2]
    const float* tkw = (const float*)d_in[2];   // top_k_weights [T, 2]
    const float* gw  = (const float*)d_in[3];   // gate_w [E, H, I]
    const float* uw  = (const float*)d_in[4];   // up_w   [E, H, I]
    const float* dw  = (const float*)d_in[5];   // down_w [E, I, H]
    float* out = (float*)d_out;                 // [T, H] fp32

    route_kernel<<<1, 256>>>(idx, tkw);
    round_x_kernel<<<(T_TOK * HID / 4 + 255) / 256, 256>>>(X);
    cudaMemsetAsync(out, 0, (size_t)out_size * sizeof(float));
    gemm1_kernel<<<dim3(MAXTILES, INTER / BN), NTHREADS>>>(gw, uw);
    gemm2_kernel<<<dim3(MAXTILES, HID / BN), NTHREADS>>>(dw, out);
}